// round 6
// baseline (speedup 1.0000x reference)
#include <cuda_runtime.h>
#include <cstdint>

// ---------------------------------------------------------------------------
// CVQNN classifier: out[b,w] = log1p(relu(c0[w] + mx'^2 + mp'^2))
//   mx'[w] = sum_k A[k][w]   *x[b,k] + bias[w]     (A = S[rows,:64], bias=d/2)
//   mp'[w] = sum_k A[k][10+w]*x[b,k] + bias[10+w]
// Single persistent kernel. Block 0 computes A/bias/c0 (row-backward
// propagation), publishes via flag. Each WARP then steals 128-row slabs from
// a global counter and runs a private 4-deep cp.async ring over 8-k chunks.
// ---------------------------------------------------------------------------

__device__ __align__(16) float g_A[64 * 20];   // A[k][o] = S[rows[o], k]
__device__ __align__(16) float g_bias[20];     // d[rows[o]] / 2
__device__ __align__(16) float g_c0[10];       // cov_term[w]/4 - 0.5
__device__ volatile int g_flag = 0;            // 0 until first publish
__device__ int g_ctr = 0;                      // next slab to steal
__device__ int g_done = 0;                     // finished blocks (reset logic)

// ---------------- f32x2 packed-math helpers --------------------------------
#define FMA2(acc, a, b) \
    asm("fma.rn.f32x2 %0, %1, %2, %0;" : "+l"(acc) : "l"(a), "l"(b))
#define MUL2(d, a, b) \
    asm("mul.rn.f32x2 %0, %1, %2;" : "=l"(d) : "l"(a), "l"(b))
#define ADD2(d, a, b) \
    asm("add.rn.f32x2 %0, %1, %2;" : "=l"(d) : "l"(a), "l"(b))
#define PACK_DUP(d, f) \
    asm("mov.b64 %0, {%1, %1};" : "=l"(d) : "f"(f))
#define UNPACK2(lo, hi, v) \
    asm("mov.b64 {%0, %1}, %2;" : "=f"(lo), "=f"(hi) : "l"(v))

// ---------------------------------------------------------------------------
// Setup (block 0 only): row-backward propagation, v^T <- v^T * F.
// ---------------------------------------------------------------------------

__device__ __forceinline__ void bs_back(float v[20], float* sv,
                                        const float* p, int start, int tid) {
    const int m = tid & 63;
    const bool lower = tid < 64;
    const bool active = (m >= start) && (m < start + ((start == 0) ? 64 : 62));
#pragma unroll
    for (int w = 0; w < 20; ++w) sv[w * 132 + tid] = v[w];
    __syncthreads();
    if (active) {
        const int rel = m - start;
        const int i = start + (rel & ~1);
        const bool is_i = (rel & 1) == 0;
        float st_, ct_, sp_, cp_;
        __sincosf(p[3 * i], &st_, &ct_);
        __sincosf(p[3 * i + 1], &sp_, &cp_);
        const int o = is_i ? (i + 1) : i;
        const int sameIdx = (lower ? 0 : 64) + o;
        const int crossIdx = (lower ? 64 : 0) + o;
        const float cA1 = (is_i ? cp_ : -cp_) * st_;
        const float cA2 = (lower ? sp_ : -sp_) * st_;
#pragma unroll
        for (int w = 0; w < 20; ++w)
            v[w] = ct_ * v[w] + cA1 * sv[w * 132 + sameIdx]
                              + cA2 * sv[w * 132 + crossIdx];
    }
    __syncthreads();
}

__device__ __forceinline__ void r_back(float v[20], float* sv,
                                       const float* p, int tid) {
    const int k = tid & 63;
    const bool lower = tid < 64;
    float c_ = 1.0f, s_ = 0.0f;
    if (k < 63) __sincosf(p[3 * k + 2], &s_, &c_);
#pragma unroll
    for (int w = 0; w < 20; ++w) sv[w * 132 + tid] = v[w];
    __syncthreads();
    const float cs = lower ? s_ : -s_;
    const int cross = tid ^ 64;
#pragma unroll
    for (int w = 0; w < 20; ++w)
        v[w] = c_ * v[w] + cs * sv[w * 132 + cross];
    __syncthreads();
}

__device__ void run_setup(float* sv,
                          const float* i1_0, const float* sq0,
                          const float* i2_0, const float* d0,
                          const float* i1_1, const float* sq1,
                          const float* i2_1, const float* d1, int tid) {
    const int k = tid & 63;
    const bool lower = tid < 64;
    float v[20];
#pragma unroll
    for (int w = 0; w < 20; ++w) {
        const int r = (w < 10) ? w : (54 + w);  // rows = [0..9, 64..73]
        v[w] = (tid == r) ? 1.0f : 0.0f;
    }
    // ---- layer 1 (leftmost in S) ----
    bs_back(v, sv, i2_1, 1, tid);
    bs_back(v, sv, i2_1, 0, tid);
    {
        const float e = lower ? __expf(-sq1[k]) : __expf(sq1[k]);
#pragma unroll
        for (int w = 0; w < 20; ++w) v[w] *= e;
    }
    r_back(v, sv, i1_1, tid);
    bs_back(v, sv, i1_1, 1, tid);
    bs_back(v, sv, i1_1, 0, tid);
    // dot0 = row_r(M_L1) . [2*disp0; 0]
#pragma unroll
    for (int w = 0; w < 20; ++w)
        sv[w * 132 + tid] = lower ? v[w] * 2.0f * d0[tid] : 0.0f;
    __syncthreads();
    if (tid < 20) {
        float s = 0.0f;
        for (int t = 0; t < 64; ++t) s += sv[tid * 132 + t];
        sv[2640 + tid] = s;
    }
    __syncthreads();
    // ---- layer 0 ----
    bs_back(v, sv, i2_0, 1, tid);
    bs_back(v, sv, i2_0, 0, tid);
    {
        const float e = lower ? __expf(-sq0[k]) : __expf(sq0[k]);
#pragma unroll
        for (int w = 0; w < 20; ++w) v[w] *= e;
    }
    r_back(v, sv, i1_0, tid);
    bs_back(v, sv, i1_0, 1, tid);
    bs_back(v, sv, i1_0, 0, tid);
    // ---- outputs ----
    if (lower) {
#pragma unroll
        for (int o = 0; o < 20; ++o) g_A[tid * 20 + o] = v[o];
    }
#pragma unroll
    for (int w = 0; w < 10; ++w)
        sv[w * 132 + tid] = v[w] * v[w] + v[w + 10] * v[w + 10];
    __syncthreads();
    if (tid < 10) {
        float s = 0.0f;
        for (int t = 0; t < 128; ++t) s += sv[tid * 132 + t];
        g_c0[tid] = 0.25f * s - 0.5f;
    }
    if (tid < 20) {
        float b = 0.5f * sv[2640 + tid];
        if (tid < 10) b += d1[tid];
        g_bias[tid] = b;
    }
    __syncthreads();
    __threadfence();
    if (tid == 0) g_flag = 1;
}

// ---------------------------------------------------------------------------
// Main: 4 warp-pipelines/block, 128-row slabs stolen dynamically.
// Per warp: ring of 4 chunk-buffers (chunk = 128 rows x 8 k-floats = 4 KB).
// ---------------------------------------------------------------------------

#define A_FLOATS   1312
#define CBUF       1024                     // floats per chunk buffer
#define WBUF       (4 * CBUF)               // 4-deep ring per warp
#define SMEM_BYTES ((A_FLOATS + 4 * WBUF) * 4)

#define CP_COMMIT() asm volatile("cp.async.commit_group;" ::: "memory")
#define CP_WAIT(N)  asm volatile("cp.async.wait_group %0;" :: "n"(N) : "memory")
#define SYNCW()     __syncwarp()

// stage chunk C (k-floats [8C, 8C+8)) of slab rowbase RB into BUF
template <int C, int BUF>
__device__ __forceinline__ void stagec(int RB, int Bm1, int lane,
                                       unsigned warpbase,
                                       const float4* __restrict__ x4) {
#pragma unroll
    for (int it = 0; it < 8; ++it) {
        const int flat = (it << 5) + lane;   // 0..255
        const int sr = flat >> 1, qq = flat & 1;
        int grow = RB + sr;
        if (grow > Bm1) grow = Bm1;
        const int f4i = (sr << 1) + (qq ^ ((sr >> 2) & 1));
        const unsigned sa = warpbase + BUF * (CBUF * 4u) + (unsigned)f4i * 16u;
        const float4* gp = x4 + (size_t)grow * 16 + C * 2 + qq;
        asm volatile("cp.async.cg.shared.global [%0], [%1], 16;"
                     :: "r"(sa), "l"(gp) : "memory");
    }
    CP_COMMIT();
}

// consume chunk C from BUF: 8 k x 4 rows x 10 FFMA2
template <int C, int BUF>
__device__ __forceinline__ void computec(const float* sx, int wid, int lane,
                                         int swz, long long (&acc)[4][10]) {
    const float4* s4 =
        reinterpret_cast<const float4*>(sx + A_FLOATS + wid * WBUF + BUF * CBUF);
#pragma unroll
    for (int g = 0; g < 2; ++g) {
        float4 xv[4];
#pragma unroll
        for (int e = 0; e < 4; ++e) {
            const int r = (e << 5) + lane;
            xv[e] = s4[(r << 1) + (g ^ swz)];
        }
#pragma unroll
        for (int q = 0; q < 4; ++q) {
            const int k = C * 8 + g * 4 + q;
            const longlong2* Ap =
                reinterpret_cast<const longlong2*>(sx + k * 20);
            long long a[10];
#pragma unroll
            for (int j = 0; j < 5; ++j) {
                const longlong2 vv = Ap[j];
                a[2 * j] = vv.x;
                a[2 * j + 1] = vv.y;
            }
#pragma unroll
            for (int e = 0; e < 4; ++e) {
                const float xk = reinterpret_cast<const float*>(&xv[e])[q];
                long long xx;
                PACK_DUP(xx, xk);
#pragma unroll
                for (int p = 0; p < 10; ++p) FMA2(acc[e][p], a[p], xx);
            }
        }
    }
}

__device__ __forceinline__ int grab(int lane) {
    int v = 0;
    if (lane == 0) v = atomicAdd(&g_ctr, 1);
    return __shfl_sync(0xffffffffu, v, 0);
}

__global__ __launch_bounds__(128, 3) void cvqnn_main(
    const float* __restrict__ x, float* __restrict__ out, int B, int nslabs,
    const float* __restrict__ i1_0, const float* __restrict__ sq0,
    const float* __restrict__ i2_0, const float* __restrict__ d0,
    const float* __restrict__ i1_1, const float* __restrict__ sq1,
    const float* __restrict__ i2_1, const float* __restrict__ d1) {
    extern __shared__ float sx[];  // [A 1312f][warp0 4x1024f]...[warp3]
    const int tid = threadIdx.x;
    const int lane = tid & 31;
    const int wid = tid >> 5;
    const int Bm1 = B - 1;
    const int swz = (lane >> 2) & 1;

    const float4* __restrict__ x4 = reinterpret_cast<const float4*>(x);
    unsigned sbase;
    asm("{ .reg .u64 t; cvta.to.shared.u64 t, %1; cvt.u32.u64 %0, t; }"
        : "=r"(sbase) : "l"(sx));
    const unsigned warpbase = sbase + A_FLOATS * 4u + (unsigned)wid * (WBUF * 4u);

    if (blockIdx.x == 0) {
        run_setup(sx, i1_0, sq0, i2_0, d0, i1_1, sq1, i2_1, d1, tid);
    } else {
        if (tid == 0)
            while (g_flag == 0) __nanosleep(64);
        __syncthreads();
        __threadfence();
    }
    __syncthreads();  // setup's smem scratch is done

    // group: A -> shared (320 float4)
    {
        const float4* gA4 = reinterpret_cast<const float4*>(g_A);
#pragma unroll
        for (int it = 0; it < 3; ++it) {
            const int i = it * 128 + tid;
            if (i < 320) {
                const unsigned sa = sbase + (unsigned)i * 16u;
                asm volatile("cp.async.cg.shared.global [%0], [%1], 16;"
                             :: "r"(sa), "l"(gA4 + i) : "memory");
            }
        }
        CP_COMMIT();
    }

    int cur = grab(lane);
    bool curv = cur < nslabs;
    if (curv) {
        const int cb = cur << 7;
        stagec<0, 0>(cb, Bm1, lane, warpbase, x4);
        stagec<1, 1>(cb, Bm1, lane, warpbase, x4);
        stagec<2, 2>(cb, Bm1, lane, warpbase, x4);
    } else {
        CP_COMMIT(); CP_COMMIT(); CP_COMMIT();
    }
    CP_WAIT(3);        // A group complete for every thread
    __syncthreads();   // A visible block-wide

    const long long* bp = reinterpret_cast<const long long*>(g_bias);
    const long long* cp0 = reinterpret_cast<const long long*>(g_c0);

    while (curv) {
        const int nxt = grab(lane);
        const bool nxtv = nxt < nslabs;
        const int cb = cur << 7;
        const int nb = nxt << 7;

        long long acc[4][10];
#pragma unroll
        for (int p = 0; p < 10; ++p) {
            const long long b = __ldg(bp + p);
#pragma unroll
            for (int e = 0; e < 4; ++e) acc[e][p] = b;
        }

        CP_WAIT(2); SYNCW(); computec<0, 0>(sx, wid, lane, swz, acc); SYNCW();
        stagec<3, 3>(cb, Bm1, lane, warpbase, x4);
        CP_WAIT(2); SYNCW(); computec<1, 1>(sx, wid, lane, swz, acc); SYNCW();
        stagec<4, 0>(cb, Bm1, lane, warpbase, x4);
        CP_WAIT(2); SYNCW(); computec<2, 2>(sx, wid, lane, swz, acc); SYNCW();
        stagec<5, 1>(cb, Bm1, lane, warpbase, x4);
        CP_WAIT(2); SYNCW(); computec<3, 3>(sx, wid, lane, swz, acc); SYNCW();
        stagec<6, 2>(cb, Bm1, lane, warpbase, x4);
        CP_WAIT(2); SYNCW(); computec<4, 0>(sx, wid, lane, swz, acc); SYNCW();
        stagec<7, 3>(cb, Bm1, lane, warpbase, x4);
        CP_WAIT(2); SYNCW(); computec<5, 1>(sx, wid, lane, swz, acc); SYNCW();
        if (nxtv) stagec<0, 0>(nb, Bm1, lane, warpbase, x4); else CP_COMMIT();
        CP_WAIT(2); SYNCW(); computec<6, 2>(sx, wid, lane, swz, acc); SYNCW();
        if (nxtv) stagec<1, 1>(nb, Bm1, lane, warpbase, x4); else CP_COMMIT();
        CP_WAIT(2); SYNCW(); computec<7, 3>(sx, wid, lane, swz, acc); SYNCW();
        if (nxtv) stagec<2, 2>(nb, Bm1, lane, warpbase, x4); else CP_COMMIT();

        // epilogue for slab 'cur' (register-only; overlaps next slab's fetch)
        long long c0p[5];
#pragma unroll
        for (int p = 0; p < 5; ++p) c0p[p] = __ldg(cp0 + p);
#pragma unroll
        for (int e = 0; e < 4; ++e) {
            const int row = cb + (e << 5) + lane;
            if (row < B) {
                float v[10];
#pragma unroll
                for (int p = 0; p < 5; ++p) {
                    long long t1, t2, s;
                    MUL2(t1, acc[e][p], acc[e][p]);
                    MUL2(t2, acc[e][5 + p], acc[e][5 + p]);
                    ADD2(s, t1, t2);
                    ADD2(s, s, c0p[p]);
                    float s0, s1;
                    UNPACK2(s0, s1, s);
#pragma unroll
                    for (int h = 0; h < 2; ++h) {
                        float nm = fmaxf((h == 0) ? s0 : s1, 0.0f);
                        const float big = __logf(1.0f + nm);
                        const float small =
                            nm * fmaf(nm, fmaf(nm, 0.33333333f, -0.5f), 1.0f);
                        v[2 * p + h] = (nm < 0.03125f) ? small : big;
                    }
                }
                float2* op = reinterpret_cast<float2*>(out + (size_t)row * 10);
#pragma unroll
                for (int j = 0; j < 5; ++j)
                    op[j] = make_float2(v[2 * j], v[2 * j + 1]);
            }
        }

        cur = nxt;
        curv = nxtv;
    }

    CP_WAIT(0);
    __syncthreads();
    if (tid == 0) {
        __threadfence();
        if (atomicAdd(&g_done, 1) == (int)gridDim.x - 1) {
            g_ctr = 0;           // reset steal pool for the next graph replay
            g_done = 0;
            __threadfence();
        }
    }
}

extern "C" void kernel_launch(void* const* d_in, const int* in_sizes, int n_in,
                              void* d_out, int out_size) {
    const float* x = (const float*)d_in[0];
    const int B = in_sizes[0] / 64;
    const int nslabs = (B + 127) >> 7;

    cudaFuncSetAttribute(cvqnn_main,
                         cudaFuncAttributeMaxDynamicSharedMemorySize,
                         SMEM_BYTES);

    int grid = 444;  // 148 SMs x 3 blocks
    if (grid > nslabs) grid = nslabs;
    cvqnn_main<<<grid, 128, SMEM_BYTES>>>(
        x, (float*)d_out, B, nslabs,
        (const float*)d_in[1], (const float*)d_in[2],
        (const float*)d_in[3], (const float*)d_in[4],
        (const float*)d_in[5], (const float*)d_in[6],
        (const float*)d_in[7], (const float*)d_in[8]);
}

// round 7
// speedup vs baseline: 1.0930x; 1.0930x over previous
#include <cuda_runtime.h>
#include <cstdint>

// ---------------------------------------------------------------------------
// CVQNN classifier: out[b,w] = log1p(relu(c0[w] + mx'^2 + mp'^2))
//   mx'[w] = sum_k A[k][w]   *x[b,k] + bias[w]     (A = S[rows,:64], bias=d/2)
//   mp'[w] = sum_k A[k][10+w]*x[b,k] + bias[10+w]
// Single launch, NON-persistent grid (one 512-row tile per block; the HW
// scheduler overlaps fill/drain across blocks). Block 0 computes A/bias/c0
// in-kernel (row-backward propagation) and publishes via flag.
// 256 threads/block, 2 rows/thread, f32x2 FFMA2, cp.async double buffering.
// ---------------------------------------------------------------------------

__device__ __align__(16) float g_A[64 * 20];   // A[k][o] = S[rows[o], k]
__device__ __align__(16) float g_bias[20];     // d[rows[o]] / 2
__device__ __align__(16) float g_c0[10];       // cov_term[w]/4 - 0.5
__device__ volatile int g_flag = 0;            // 0 until first publish

// ---------------- f32x2 packed-math helpers --------------------------------
#define FMA2(acc, a, b) \
    asm("fma.rn.f32x2 %0, %1, %2, %0;" : "+l"(acc) : "l"(a), "l"(b))
#define MUL2(d, a, b) \
    asm("mul.rn.f32x2 %0, %1, %2;" : "=l"(d) : "l"(a), "l"(b))
#define ADD2(d, a, b) \
    asm("add.rn.f32x2 %0, %1, %2;" : "=l"(d) : "l"(a), "l"(b))
#define PACK_DUP(d, f) \
    asm("mov.b64 %0, {%1, %1};" : "=l"(d) : "f"(f))
#define UNPACK2(lo, hi, v) \
    asm("mov.b64 {%0, %1}, %2;" : "=f"(lo), "=f"(hi) : "l"(v))

// ---------------------------------------------------------------------------
// Setup (block 0 only): row-backward propagation, v^T <- v^T * F.
// Only threads 0..127 carry state; all threads hit the barriers.
// ---------------------------------------------------------------------------

__device__ __forceinline__ void bs_back(float v[20], float* sv,
                                        const float* p, int start, int tid) {
    const int m = tid & 63;
    const bool lower = tid < 64;
    const bool carrier = tid < 128;
    const bool active =
        carrier && (m >= start) && (m < start + ((start == 0) ? 64 : 62));
    if (carrier) {
#pragma unroll
        for (int w = 0; w < 20; ++w) sv[w * 132 + tid] = v[w];
    }
    __syncthreads();
    if (active) {
        const int rel = m - start;
        const int i = start + (rel & ~1);
        const bool is_i = (rel & 1) == 0;
        float st_, ct_, sp_, cp_;
        __sincosf(p[3 * i], &st_, &ct_);
        __sincosf(p[3 * i + 1], &sp_, &cp_);
        const int o = is_i ? (i + 1) : i;
        const int sameIdx = (lower ? 0 : 64) + o;
        const int crossIdx = (lower ? 64 : 0) + o;
        const float cA1 = (is_i ? cp_ : -cp_) * st_;
        const float cA2 = (lower ? sp_ : -sp_) * st_;
#pragma unroll
        for (int w = 0; w < 20; ++w)
            v[w] = ct_ * v[w] + cA1 * sv[w * 132 + sameIdx]
                              + cA2 * sv[w * 132 + crossIdx];
    }
    __syncthreads();
}

__device__ __forceinline__ void r_back(float v[20], float* sv,
                                       const float* p, int tid) {
    const int k = tid & 63;
    const bool lower = tid < 64;
    const bool carrier = tid < 128;
    float c_ = 1.0f, s_ = 0.0f;
    if (carrier && k < 63) __sincosf(p[3 * k + 2], &s_, &c_);
    if (carrier) {
#pragma unroll
        for (int w = 0; w < 20; ++w) sv[w * 132 + tid] = v[w];
    }
    __syncthreads();
    if (carrier) {
        const float cs = lower ? s_ : -s_;
        const int cross = tid ^ 64;
#pragma unroll
        for (int w = 0; w < 20; ++w)
            v[w] = c_ * v[w] + cs * sv[w * 132 + cross];
    }
    __syncthreads();
}

__device__ void run_setup(float* sv,
                          const float* i1_0, const float* sq0,
                          const float* i2_0, const float* d0,
                          const float* i1_1, const float* sq1,
                          const float* i2_1, const float* d1, int tid) {
    const int k = tid & 63;
    const bool lower = tid < 64;
    const bool carrier = tid < 128;
    float v[20];
#pragma unroll
    for (int w = 0; w < 20; ++w) {
        const int r = (w < 10) ? w : (54 + w);  // rows = [0..9, 64..73]
        v[w] = (tid == r) ? 1.0f : 0.0f;
    }
    // ---- layer 1 (leftmost in S) ----
    bs_back(v, sv, i2_1, 1, tid);
    bs_back(v, sv, i2_1, 0, tid);
    if (carrier) {
        const float e = lower ? __expf(-sq1[k]) : __expf(sq1[k]);
#pragma unroll
        for (int w = 0; w < 20; ++w) v[w] *= e;
    }
    r_back(v, sv, i1_1, tid);
    bs_back(v, sv, i1_1, 1, tid);
    bs_back(v, sv, i1_1, 0, tid);
    // dot0 = row_r(M_L1) . [2*disp0; 0]
    if (carrier) {
#pragma unroll
        for (int w = 0; w < 20; ++w)
            sv[w * 132 + tid] = lower ? v[w] * 2.0f * d0[tid] : 0.0f;
    }
    __syncthreads();
    if (tid < 20) {
        float s = 0.0f;
        for (int t = 0; t < 64; ++t) s += sv[tid * 132 + t];
        sv[2640 + tid] = s;
    }
    __syncthreads();
    // ---- layer 0 ----
    bs_back(v, sv, i2_0, 1, tid);
    bs_back(v, sv, i2_0, 0, tid);
    if (carrier) {
        const float e = lower ? __expf(-sq0[k]) : __expf(sq0[k]);
#pragma unroll
        for (int w = 0; w < 20; ++w) v[w] *= e;
    }
    r_back(v, sv, i1_0, tid);
    bs_back(v, sv, i1_0, 1, tid);
    bs_back(v, sv, i1_0, 0, tid);
    // ---- outputs ----
    if (lower) {
#pragma unroll
        for (int o = 0; o < 20; ++o) g_A[tid * 20 + o] = v[o];
    }
    if (carrier) {
#pragma unroll
        for (int w = 0; w < 10; ++w)
            sv[w * 132 + tid] = v[w] * v[w] + v[w + 10] * v[w + 10];
    }
    __syncthreads();
    if (tid < 10) {
        float s = 0.0f;
        for (int t = 0; t < 128; ++t) s += sv[tid * 132 + t];
        g_c0[tid] = 0.25f * s - 0.5f;
    }
    if (tid < 20) {
        float b = 0.5f * sv[2640 + tid];
        if (tid < 10) b += d1[tid];
        g_bias[tid] = b;
    }
    __syncthreads();
    __threadfence();
    if (tid == 0) g_flag = 1;
}

// ---------------------------------------------------------------------------
// Main pipeline: 256 threads, 2 rows/thread, one 512-row tile per block.
// smem: A (1312 floats) + 2 x-buffers of 512 rows x 16 floats, XOR-swizzled
// (q ^= (row>>1)&3) for conflict-free LDS.128 without padding.
// ---------------------------------------------------------------------------

#define A_FLOATS   1312
#define BUF_FLOATS 8192                     // 512 * 16
#define SMEM_BYTES ((A_FLOATS + 2 * BUF_FLOATS) * 4)

#define CP_COMMIT() asm volatile("cp.async.commit_group;" ::: "memory")
#define CP_WAIT(N)  asm volatile("cp.async.wait_group %0;" :: "n"(N) : "memory")

// stage quarter-row QH of 512 rows into buffer BUF (8 x 16B per thread)
#define STAGE(QH, BUF)                                                        \
    do {                                                                      \
        _Pragma("unroll")                                                     \
        for (int it = 0; it < 8; ++it) {                                      \
            const int flat = (it << 8) + tid;                                 \
            const int sr = flat >> 2, q = flat & 3;                           \
            int grow = base + sr;                                             \
            if (grow > Bm1) grow = Bm1;                                       \
            const int f4i = (sr << 2) + (q ^ ((sr >> 1) & 3));                \
            const unsigned sa = sbase + (A_FLOATS * 4u) +                     \
                                (BUF) * (BUF_FLOATS * 4u) + (unsigned)f4i * 16u; \
            const float4* gp = x4 + (size_t)grow * 16 + (QH) * 4 + q;         \
            asm volatile("cp.async.cg.shared.global [%0], [%1], 16;"          \
                         :: "r"(sa), "l"(gp) : "memory");                     \
        }                                                                     \
        CP_COMMIT();                                                          \
    } while (0)

// consume quarter QH from BUF: 16 k x 2 rows x 10 FFMA2
#define COMPUTE(QH, BUF)                                                      \
    do {                                                                      \
        const float4* s4 =                                                    \
            reinterpret_cast<const float4*>(sx + A_FLOATS + (BUF) * BUF_FLOATS); \
        _Pragma("unroll")                                                     \
        for (int kk = 0; kk < 4; ++kk) {                                      \
            float4 xv[2];                                                     \
            _Pragma("unroll")                                                 \
            for (int e = 0; e < 2; ++e)                                       \
                xv[e] = s4[(((e << 8) + tid) << 2) + (kk ^ sw)];              \
            _Pragma("unroll")                                                 \
            for (int q = 0; q < 4; ++q) {                                     \
                const int k = (QH) * 16 + kk * 4 + q;                         \
                const longlong2* Ap =                                         \
                    reinterpret_cast<const longlong2*>(sx + k * 20);          \
                long long a[10];                                              \
                _Pragma("unroll")                                             \
                for (int j = 0; j < 5; ++j) {                                 \
                    const longlong2 vv = Ap[j];                               \
                    a[2 * j] = vv.x;                                          \
                    a[2 * j + 1] = vv.y;                                      \
                }                                                             \
                _Pragma("unroll")                                             \
                for (int e = 0; e < 2; ++e) {                                 \
                    const float xk = reinterpret_cast<const float*>(&xv[e])[q]; \
                    long long xx;                                             \
                    PACK_DUP(xx, xk);                                         \
                    _Pragma("unroll")                                         \
                    for (int p = 0; p < 10; ++p) FMA2(acc[e][p], a[p], xx);   \
                }                                                             \
            }                                                                 \
        }                                                                     \
    } while (0)

__global__ __launch_bounds__(256, 2) void cvqnn_main(
    const float* __restrict__ x, float* __restrict__ out, int B,
    const float* __restrict__ i1_0, const float* __restrict__ sq0,
    const float* __restrict__ i2_0, const float* __restrict__ d0,
    const float* __restrict__ i1_1, const float* __restrict__ sq1,
    const float* __restrict__ i2_1, const float* __restrict__ d1) {
    extern __shared__ float sx[];  // [A 1312f][buf0 8192f][buf1 8192f]
    const int tid = threadIdx.x;
    const int base = blockIdx.x << 9;  // * 512 rows
    const int Bm1 = B - 1;
    const int sw = (tid >> 1) & 3;

    const float4* __restrict__ x4 = reinterpret_cast<const float4*>(x);
    unsigned sbase;
    asm("{ .reg .u64 t; cvta.to.shared.u64 t, %1; cvt.u32.u64 %0, t; }"
        : "=r"(sbase) : "l"(sx));

    if (blockIdx.x == 0) {
        run_setup(sx, i1_0, sq0, i2_0, d0, i1_1, sq1, i2_1, d1, tid);
    } else {
        if (tid == 0)
            while (g_flag == 0) __nanosleep(64);
        __syncthreads();
        __threadfence();
    }
    __syncthreads();  // setup scratch in sx is done

    // group 1: A -> shared (320 float4)
    {
        const float4* gA4 = reinterpret_cast<const float4*>(g_A);
#pragma unroll
        for (int it = 0; it < 2; ++it) {
            const int i = it * 256 + tid;
            if (i < 320) {
                const unsigned sa = sbase + (unsigned)i * 16u;
                asm volatile("cp.async.cg.shared.global [%0], [%1], 16;"
                             :: "r"(sa), "l"(gA4 + i) : "memory");
            }
        }
        CP_COMMIT();
    }

    STAGE(0, 0);  // group 2
    STAGE(1, 1);  // group 3

    // accumulators start at bias
    long long acc[2][10];
    {
        const long long* bp = reinterpret_cast<const long long*>(g_bias);
#pragma unroll
        for (int p = 0; p < 10; ++p) {
            const long long b = __ldg(bp + p);
            acc[0][p] = b;
            acc[1][p] = b;
        }
    }

    CP_WAIT(1); __syncthreads();        // A + q0 landed
    COMPUTE(0, 0); __syncthreads();
    STAGE(2, 0);
    CP_WAIT(1); __syncthreads();        // q1 landed
    COMPUTE(1, 1); __syncthreads();
    STAGE(3, 1);
    CP_WAIT(1); __syncthreads();        // q2 landed
    COMPUTE(2, 0); __syncthreads();
    CP_WAIT(0); __syncthreads();        // q3 landed
    COMPUTE(3, 1);

    // epilogue
    long long c0p[5];
    {
        const long long* cp0 = reinterpret_cast<const long long*>(g_c0);
#pragma unroll
        for (int p = 0; p < 5; ++p) c0p[p] = __ldg(cp0 + p);
    }
#pragma unroll
    for (int e = 0; e < 2; ++e) {
        const int row = base + (e << 8) + tid;
        if (row < B) {
            float v[10];
#pragma unroll
            for (int p = 0; p < 5; ++p) {
                long long t1, t2, s;
                MUL2(t1, acc[e][p], acc[e][p]);
                MUL2(t2, acc[e][5 + p], acc[e][5 + p]);
                ADD2(s, t1, t2);
                ADD2(s, s, c0p[p]);
                float s0, s1;
                UNPACK2(s0, s1, s);
#pragma unroll
                for (int h = 0; h < 2; ++h) {
                    float nm = fmaxf((h == 0) ? s0 : s1, 0.0f);
                    const float big = __logf(1.0f + nm);
                    const float small =
                        nm * fmaf(nm, fmaf(nm, 0.33333333f, -0.5f), 1.0f);
                    v[2 * p + h] = (nm < 0.03125f) ? small : big;
                }
            }
            float2* op = reinterpret_cast<float2*>(out + (size_t)row * 10);
#pragma unroll
            for (int j = 0; j < 5; ++j)
                op[j] = make_float2(v[2 * j], v[2 * j + 1]);
        }
    }
}

extern "C" void kernel_launch(void* const* d_in, const int* in_sizes, int n_in,
                              void* d_out, int out_size) {
    const float* x = (const float*)d_in[0];
    const int B = in_sizes[0] / 64;
    const int ntiles = (B + 511) >> 9;

    cudaFuncSetAttribute(cvqnn_main,
                         cudaFuncAttributeMaxDynamicSharedMemorySize,
                         SMEM_BYTES);

    cvqnn_main<<<ntiles, 256, SMEM_BYTES>>>(
        x, (float*)d_out, B,
        (const float*)d_in[1], (const float*)d_in[2],
        (const float*)d_in[3], (const float*)d_in[4],
        (const float*)d_in[5], (const float*)d_in[6],
        (const float*)d_in[7], (const float*)d_in[8]);
}

// round 8
// speedup vs baseline: 1.1693x; 1.0698x over previous
#include <cuda_runtime.h>
#include <cstdint>

// ---------------------------------------------------------------------------
// CVQNN classifier: out[b,w] = log1p(relu(c0[w] + mx'^2 + mp'^2))
//   mx'[w] = sum_k A[k][w]   *x[b,k] + bias[w]     (A = S[rows,:64], bias=d/2)
//   mp'[w] = sum_k A[k][10+w]*x[b,k] + bias[10+w]
// Single launch, non-persistent grid (one 512-row tile per block; HW block
// scheduler overlaps fill/drain across co-resident blocks). Block 0 computes
// A/bias/c0 in-kernel (row-backward propagation), publishes via flag.
// 128 threads/block, 4 rows/thread, f32x2 FFMA2, cp.async double buffering.
// ---------------------------------------------------------------------------

__device__ __align__(16) float g_A[64 * 20];   // A[k][o] = S[rows[o], k]
__device__ __align__(16) float g_bias[20];     // d[rows[o]] / 2
__device__ __align__(16) float g_c0[10];       // cov_term[w]/4 - 0.5
__device__ volatile int g_flag = 0;            // 0 until first publish

// ---------------- f32x2 packed-math helpers --------------------------------
#define FMA2(acc, a, b) \
    asm("fma.rn.f32x2 %0, %1, %2, %0;" : "+l"(acc) : "l"(a), "l"(b))
#define MUL2(d, a, b) \
    asm("mul.rn.f32x2 %0, %1, %2;" : "=l"(d) : "l"(a), "l"(b))
#define ADD2(d, a, b) \
    asm("add.rn.f32x2 %0, %1, %2;" : "=l"(d) : "l"(a), "l"(b))
#define PACK_DUP(d, f) \
    asm("mov.b64 %0, {%1, %1};" : "=l"(d) : "f"(f))
#define UNPACK2(lo, hi, v) \
    asm("mov.b64 {%0, %1}, %2;" : "=f"(lo), "=f"(hi) : "l"(v))

// ---------------------------------------------------------------------------
// Setup (block 0 only, 128 threads): row-backward propagation v^T <- v^T * F.
// Thread t holds element t of all 20 tracked rows; exchange via shared.
// ---------------------------------------------------------------------------

__device__ __forceinline__ void bs_back(float v[20], float* sv,
                                        const float* p, int start, int tid) {
    const int m = tid & 63;
    const bool lower = tid < 64;
    const bool active = (m >= start) && (m < start + ((start == 0) ? 64 : 62));
#pragma unroll
    for (int w = 0; w < 20; ++w) sv[w * 132 + tid] = v[w];
    __syncthreads();
    if (active) {
        const int rel = m - start;
        const int i = start + (rel & ~1);
        const bool is_i = (rel & 1) == 0;
        float st_, ct_, sp_, cp_;
        __sincosf(p[3 * i], &st_, &ct_);
        __sincosf(p[3 * i + 1], &sp_, &cp_);
        const int o = is_i ? (i + 1) : i;
        const int sameIdx = (lower ? 0 : 64) + o;
        const int crossIdx = (lower ? 64 : 0) + o;
        const float cA1 = (is_i ? cp_ : -cp_) * st_;
        const float cA2 = (lower ? sp_ : -sp_) * st_;
#pragma unroll
        for (int w = 0; w < 20; ++w)
            v[w] = ct_ * v[w] + cA1 * sv[w * 132 + sameIdx]
                              + cA2 * sv[w * 132 + crossIdx];
    }
    __syncthreads();
}

__device__ __forceinline__ void r_back(float v[20], float* sv,
                                       const float* p, int tid) {
    const int k = tid & 63;
    const bool lower = tid < 64;
    float c_ = 1.0f, s_ = 0.0f;
    if (k < 63) __sincosf(p[3 * k + 2], &s_, &c_);
#pragma unroll
    for (int w = 0; w < 20; ++w) sv[w * 132 + tid] = v[w];
    __syncthreads();
    const float cs = lower ? s_ : -s_;
    const int cross = tid ^ 64;
#pragma unroll
    for (int w = 0; w < 20; ++w)
        v[w] = c_ * v[w] + cs * sv[w * 132 + cross];
    __syncthreads();
}

__device__ void run_setup(float* sv,
                          const float* i1_0, const float* sq0,
                          const float* i2_0, const float* d0,
                          const float* i1_1, const float* sq1,
                          const float* i2_1, const float* d1, int tid) {
    const int k = tid & 63;
    const bool lower = tid < 64;
    float v[20];
#pragma unroll
    for (int w = 0; w < 20; ++w) {
        const int r = (w < 10) ? w : (54 + w);  // rows = [0..9, 64..73]
        v[w] = (tid == r) ? 1.0f : 0.0f;
    }
    // ---- layer 1 (leftmost in S) ----
    bs_back(v, sv, i2_1, 1, tid);
    bs_back(v, sv, i2_1, 0, tid);
    {
        const float e = lower ? __expf(-sq1[k]) : __expf(sq1[k]);
#pragma unroll
        for (int w = 0; w < 20; ++w) v[w] *= e;
    }
    r_back(v, sv, i1_1, tid);
    bs_back(v, sv, i1_1, 1, tid);
    bs_back(v, sv, i1_1, 0, tid);
    // dot0 = row_r(M_L1) . [2*disp0; 0]
#pragma unroll
    for (int w = 0; w < 20; ++w)
        sv[w * 132 + tid] = lower ? v[w] * 2.0f * d0[tid] : 0.0f;
    __syncthreads();
    if (tid < 20) {
        float s = 0.0f;
        for (int t = 0; t < 64; ++t) s += sv[tid * 132 + t];
        sv[2640 + tid] = s;
    }
    __syncthreads();
    // ---- layer 0 ----
    bs_back(v, sv, i2_0, 1, tid);
    bs_back(v, sv, i2_0, 0, tid);
    {
        const float e = lower ? __expf(-sq0[k]) : __expf(sq0[k]);
#pragma unroll
        for (int w = 0; w < 20; ++w) v[w] *= e;
    }
    r_back(v, sv, i1_0, tid);
    bs_back(v, sv, i1_0, 1, tid);
    bs_back(v, sv, i1_0, 0, tid);
    // ---- outputs ----
    if (lower) {
#pragma unroll
        for (int o = 0; o < 20; ++o) g_A[tid * 20 + o] = v[o];
    }
#pragma unroll
    for (int w = 0; w < 10; ++w)
        sv[w * 132 + tid] = v[w] * v[w] + v[w + 10] * v[w + 10];
    __syncthreads();
    if (tid < 10) {
        float s = 0.0f;
        for (int t = 0; t < 128; ++t) s += sv[tid * 132 + t];
        g_c0[tid] = 0.25f * s - 0.5f;
    }
    if (tid < 20) {
        float b = 0.5f * sv[2640 + tid];
        if (tid < 10) b += d1[tid];
        g_bias[tid] = b;
    }
    __syncthreads();
    __threadfence();
    if (tid == 0) g_flag = 1;
}

// ---------------------------------------------------------------------------
// Main pipeline: 128 threads, 4 rows/thread, one 512-row tile per block.
// smem: A (1312 floats) + 2 x-buffers of 512 rows x 16 floats, XOR-swizzled
// (q ^= (row>>1)&3) for conflict-free LDS.128 without padding.
// ---------------------------------------------------------------------------

#define A_FLOATS   1312
#define BUF_FLOATS 8192                     // 512 * 16
#define SMEM_BYTES ((A_FLOATS + 2 * BUF_FLOATS) * 4)

#define CP_COMMIT() asm volatile("cp.async.commit_group;" ::: "memory")
#define CP_WAIT(N)  asm volatile("cp.async.wait_group %0;" :: "n"(N) : "memory")

// stage quarter-row QH of 512 rows into buffer BUF (16 x 16B per thread)
#define STAGE(QH, BUF)                                                        \
    do {                                                                      \
        _Pragma("unroll")                                                     \
        for (int it = 0; it < 16; ++it) {                                     \
            const int flat = (it << 7) + tid;                                 \
            const int sr = flat >> 2, q = flat & 3;                           \
            int grow = base + sr;                                             \
            if (grow > Bm1) grow = Bm1;                                       \
            const int f4i = (sr << 2) + (q ^ ((sr >> 1) & 3));                \
            const unsigned sa = sbase + (A_FLOATS * 4u) +                     \
                                (BUF) * (BUF_FLOATS * 4u) + (unsigned)f4i * 16u; \
            const float4* gp = x4 + (size_t)grow * 16 + (QH) * 4 + q;         \
            asm volatile("cp.async.cg.shared.global [%0], [%1], 16;"          \
                         :: "r"(sa), "l"(gp) : "memory");                     \
        }                                                                     \
        CP_COMMIT();                                                          \
    } while (0)

// consume quarter QH from BUF: 16 k x 4 rows x 10 FFMA2
#define COMPUTE(QH, BUF)                                                      \
    do {                                                                      \
        const float4* s4 =                                                    \
            reinterpret_cast<const float4*>(sx + A_FLOATS + (BUF) * BUF_FLOATS); \
        _Pragma("unroll")                                                     \
        for (int kk = 0; kk < 4; ++kk) {                                      \
            float4 xv[4];                                                     \
            _Pragma("unroll")                                                 \
            for (int e = 0; e < 4; ++e)                                       \
                xv[e] = s4[(((e << 7) + tid) << 2) + (kk ^ sw)];              \
            _Pragma("unroll")                                                 \
            for (int q = 0; q < 4; ++q) {                                     \
                const int k = (QH) * 16 + kk * 4 + q;                         \
                const longlong2* Ap =                                         \
                    reinterpret_cast<const longlong2*>(sx + k * 20);          \
                long long a[10];                                              \
                _Pragma("unroll")                                             \
                for (int j = 0; j < 5; ++j) {                                 \
                    const longlong2 vv = Ap[j];                               \
                    a[2 * j] = vv.x;                                          \
                    a[2 * j + 1] = vv.y;                                      \
                }                                                             \
                _Pragma("unroll")                                             \
                for (int e = 0; e < 4; ++e) {                                 \
                    const float xk = reinterpret_cast<const float*>(&xv[e])[q]; \
                    long long xx;                                             \
                    PACK_DUP(xx, xk);                                         \
                    _Pragma("unroll")                                         \
                    for (int p = 0; p < 10; ++p) FMA2(acc[e][p], a[p], xx);   \
                }                                                             \
            }                                                                 \
        }                                                                     \
    } while (0)

__global__ __launch_bounds__(128, 3) void cvqnn_main(
    const float* __restrict__ x, float* __restrict__ out, int B,
    const float* __restrict__ i1_0, const float* __restrict__ sq0,
    const float* __restrict__ i2_0, const float* __restrict__ d0,
    const float* __restrict__ i1_1, const float* __restrict__ sq1,
    const float* __restrict__ i2_1, const float* __restrict__ d1) {
    extern __shared__ float sx[];  // [A 1312f][buf0 8192f][buf1 8192f]
    const int tid = threadIdx.x;
    const int base = blockIdx.x << 9;  // * 512 rows
    const int Bm1 = B - 1;
    const int sw = (tid >> 1) & 3;

    const float4* __restrict__ x4 = reinterpret_cast<const float4*>(x);
    unsigned sbase;
    asm("{ .reg .u64 t; cvta.to.shared.u64 t, %1; cvt.u32.u64 %0, t; }"
        : "=r"(sbase) : "l"(sx));

    if (blockIdx.x == 0) {
        run_setup(sx, i1_0, sq0, i2_0, d0, i1_1, sq1, i2_1, d1, tid);
    } else {
        if (tid == 0)
            while (g_flag == 0) __nanosleep(64);
        __syncthreads();
        __threadfence();
    }
    __syncthreads();  // setup scratch in sx is done

    // group 1: A -> shared (320 float4)
    {
        const float4* gA4 = reinterpret_cast<const float4*>(g_A);
#pragma unroll
        for (int it = 0; it < 3; ++it) {
            const int i = it * 128 + tid;
            if (i < 320) {
                const unsigned sa = sbase + (unsigned)i * 16u;
                asm volatile("cp.async.cg.shared.global [%0], [%1], 16;"
                             :: "r"(sa), "l"(gA4 + i) : "memory");
            }
        }
        CP_COMMIT();
    }

    STAGE(0, 0);  // group 2
    STAGE(1, 1);  // group 3

    // accumulators start at bias
    long long acc[4][10];
    {
        const long long* bp = reinterpret_cast<const long long*>(g_bias);
#pragma unroll
        for (int p = 0; p < 10; ++p) {
            const long long b = __ldg(bp + p);
#pragma unroll
            for (int e = 0; e < 4; ++e) acc[e][p] = b;
        }
    }

    CP_WAIT(1); __syncthreads();        // A + q0 landed
    COMPUTE(0, 0); __syncthreads();
    STAGE(2, 0);
    CP_WAIT(1); __syncthreads();        // q1 landed
    COMPUTE(1, 1); __syncthreads();
    STAGE(3, 1);
    CP_WAIT(1); __syncthreads();        // q2 landed
    COMPUTE(2, 0); __syncthreads();
    CP_WAIT(0); __syncthreads();        // q3 landed
    COMPUTE(3, 1);

    // epilogue
    long long c0p[5];
    {
        const long long* cp0 = reinterpret_cast<const long long*>(g_c0);
#pragma unroll
        for (int p = 0; p < 5; ++p) c0p[p] = __ldg(cp0 + p);
    }
#pragma unroll
    for (int e = 0; e < 4; ++e) {
        const int row = base + (e << 7) + tid;
        if (row < B) {
            float v[10];
#pragma unroll
            for (int p = 0; p < 5; ++p) {
                long long t1, t2, s;
                MUL2(t1, acc[e][p], acc[e][p]);
                MUL2(t2, acc[e][5 + p], acc[e][5 + p]);
                ADD2(s, t1, t2);
                ADD2(s, s, c0p[p]);
                float s0, s1;
                UNPACK2(s0, s1, s);
#pragma unroll
                for (int h = 0; h < 2; ++h) {
                    float nm = fmaxf((h == 0) ? s0 : s1, 0.0f);
                    const float big = __logf(1.0f + nm);
                    const float small =
                        nm * fmaf(nm, fmaf(nm, 0.33333333f, -0.5f), 1.0f);
                    v[2 * p + h] = (nm < 0.03125f) ? small : big;
                }
            }
            float2* op = reinterpret_cast<float2*>(out + (size_t)row * 10);
#pragma unroll
            for (int j = 0; j < 5; ++j)
                op[j] = make_float2(v[2 * j], v[2 * j + 1]);
        }
    }
}

extern "C" void kernel_launch(void* const* d_in, const int* in_sizes, int n_in,
                              void* d_out, int out_size) {
    const float* x = (const float*)d_in[0];
    const int B = in_sizes[0] / 64;
    const int ntiles = (B + 511) >> 9;

    cudaFuncSetAttribute(cvqnn_main,
                         cudaFuncAttributeMaxDynamicSharedMemorySize,
                         SMEM_BYTES);

    cvqnn_main<<<ntiles, 128, SMEM_BYTES>>>(
        x, (float*)d_out, B,
        (const float*)d_in[1], (const float*)d_in[2],
        (const float*)d_in[3], (const float*)d_in[4],
        (const float*)d_in[5], (const float*)d_in[6],
        (const float*)d_in[7], (const float*)d_in[8]);
}